// round 10
// baseline (speedup 1.0000x reference)
#include <cuda_runtime.h>
#include <math.h>

// ---------------- problem constants ----------------
constexpr int Bn = 16, Tn = 16, Sn = 196, Dn = 768;
constexpr int NHn = 4, Gn = 14, GUPn = 56, UPN = GUPn * GUPn;
constexpr int BT = Bn * Tn;      // 256
constexpr float RSQRT_DH = 0.07216878364870323f;  // 1/sqrt(192)

#define DEV static __device__ __forceinline__

// ---------------- scratch (device globals; no allocations allowed) ----------
__device__ float g_qh[Dn];
__device__ float g_wk[NHn * Dn];
__device__ float g_sbias[NHn];
__device__ float g_normed[(size_t)BT * Sn * Dn];   // 154 MB
__device__ float g_scores[BT * NHn * Sn];
__device__ float g_probs[BT * NHn * Sn];
__device__ float g_obj[BT * Sn];
__device__ int   g_cell[BT * 2];
__device__ float g_cxy0[BT * 2];
__device__ float g_pooledX[BT * NHn * Dn];
__device__ float g_local[BT * Dn];
__device__ float g_ctx[BT * Dn];
__device__ float g_ctx2[BT * Dn];
__device__ float g_A1[BT * 2 * Dn];
__device__ float g_h1[BT * 256];
__device__ float g_h2[BT * 128];

// Scratch selector: device-side resolution of scratch buffers.
// NEVER pass __device__ globals as kernel args from host code — on GB300
// (ATS/HMM) the host shadow address is dereferenceable by the GPU and reads
// silently return zeros instead of faulting.
DEV float* scratch_ptr(int id) {
    switch (id) {
        case 0: return g_pooledX;
        case 1: return g_ctx;
        case 2: return g_ctx2;
        case 3: return g_A1;
        case 4: return g_h1;
        case 5: return g_h2;
    }
    return nullptr;
}

// ---------------- helpers ----------------
DEV float warpRedSum(float v) {
    #pragma unroll
    for (int o = 16; o; o >>= 1) v += __shfl_xor_sync(0xffffffffu, v, o);
    return v;
}
DEV float warpRedMax(float v) {
    #pragma unroll
    for (int o = 16; o; o >>= 1) v = fmaxf(v, __shfl_xor_sync(0xffffffffu, v, o));
    return v;
}
DEV float geluf(float x) { return 0.5f * x * (1.0f + erff(x * 0.70710678118654752f)); }
DEV float clampf(float x, float lo, float hi) { return fminf(fmaxf(x, lo), hi); }

// ---------------- K1a: qh[j] = query . Wq[j] + bq[j] ------------------------
__global__ void __launch_bounds__(128) k_prep_qh(const float* __restrict__ query,
                                                 const float* __restrict__ ipw,
                                                 const float* __restrict__ ipb) {
    int j = blockIdx.x, tid = threadIdx.x;
    float p = 0.f;
    const float* row = ipw + (size_t)j * Dn;
    for (int k = tid; k < Dn; k += 128) p += query[k] * row[k];
    __shared__ float r4[4];
    p = warpRedSum(p);
    if ((tid & 31) == 0) r4[tid >> 5] = p;
    __syncthreads();
    if (tid == 0) g_qh[j] = r4[0] + r4[1] + r4[2] + r4[3] + ipb[j];
}

// ---------------- K1b: wk_eff[h][d] = sum_j qh[h,j] * Wk[h*192+j][d] --------
__global__ void __launch_bounds__(768) k_prep_wk2(const float* __restrict__ ipw,
                                                  const float* __restrict__ ipb) {
    int h = blockIdx.x, tid = threadIdx.x;
    __shared__ float qs[192];
    if (tid < 192) qs[tid] = g_qh[h * 192 + tid];
    __syncthreads();
    float acc = 0.f;
    const float* base = ipw + (size_t)(Dn + h * 192) * Dn;
    for (int j = 0; j < 192; j++) acc += qs[j] * base[(size_t)j * Dn + tid];
    g_wk[h * Dn + tid] = acc;
    if (tid == 0) {
        float s = 0.f;
        for (int j = 0; j < 192; j++) s += qs[j] * ipb[Dn + h * 192 + j];
        g_sbias[h] = s;
    }
}

// ---------------- K2: per-token LN + scores + obj (block per token) ---------
__global__ void __launch_bounds__(768) k_ln_score(const float* __restrict__ tokens,
                                                  const float* __restrict__ lnw,
                                                  const float* __restrict__ lnb,
                                                  const float* __restrict__ objw,
                                                  const float* __restrict__ objb) {
    __shared__ float red[128];
    int row = blockIdx.x, tid = threadIdx.x, w = tid >> 5, l = tid & 31;
    float x = tokens[(size_t)row * Dn + tid];
    float s1 = warpRedSum(x), s2 = warpRedSum(x * x);
    if (l == 0) { red[w] = s1; red[24 + w] = s2; }
    __syncthreads();
    if (tid == 0) {
        float a = 0.f, b = 0.f;
        for (int i = 0; i < 24; i++) { a += red[i]; b += red[24 + i]; }
        red[120] = a; red[121] = b;
    }
    __syncthreads();
    float m = red[120] * (1.f / 768.f);
    float var = red[121] * (1.f / 768.f) - m * m;
    float r = rsqrtf(var + 1e-5f);
    float n = (x - m) * r * lnw[tid] + lnb[tid];
    g_normed[(size_t)row * Dn + tid] = n;
    float p0 = n * g_wk[tid];
    float p1 = n * g_wk[Dn + tid];
    float p2 = n * g_wk[2 * Dn + tid];
    float p3 = n * g_wk[3 * Dn + tid];
    float p4 = n * objw[tid];
    p0 = warpRedSum(p0); p1 = warpRedSum(p1); p2 = warpRedSum(p2);
    p3 = warpRedSum(p3); p4 = warpRedSum(p4);
    if (l == 0) {
        red[w] = p0; red[24 + w] = p1; red[48 + w] = p2;
        red[72 + w] = p3; red[96 + w] = p4;
    }
    __syncthreads();
    if (tid < 5) {
        float a = 0.f;
        for (int i = 0; i < 24; i++) a += red[tid * 24 + i];
        red[120 + tid] = a;
    }
    __syncthreads();
    if (tid == 0) {
        int bt = row / Sn, s = row - bt * Sn;
        for (int h = 0; h < NHn; h++)
            g_scores[(bt * NHn + h) * Sn + s] = (red[120 + h] + g_sbias[h]) * RSQRT_DH;
        g_obj[row] = red[124] + objb[0];
    }
}

// ---------------- K3: per-(bt,head) softmax (warp each) ---------------------
__global__ void __launch_bounds__(128) k_softmax() {
    int bt = blockIdx.x, h = threadIdx.x >> 5, l = threadIdx.x & 31;
    const float* sc = g_scores + (bt * NHn + h) * Sn;
    float* pr = g_probs + (bt * NHn + h) * Sn;
    float mx = -1e30f;
    for (int s = l; s < Sn; s += 32) mx = fmaxf(mx, sc[s]);
    mx = warpRedMax(mx);
    float sum = 0.f;
    for (int s = l; s < Sn; s += 32) {
        float e = expf(sc[s] - mx);
        pr[s] = e; sum += e;
    }
    sum = warpRedSum(sum);
    float inv = 1.f / sum;
    for (int s = l; s < Sn; s += 32) pr[s] *= inv;
}

// ---------------- K4: dense-Wu upsample + spatial softmax + coords ----------
__global__ void __launch_bounds__(256) k_spatial(const float* __restrict__ temperature) {
    __shared__ float sWu[GUPn * Gn];     // 56 x 14
    __shared__ float sT1[Gn * GUPn];     // 14 x 56
    __shared__ float sObj[Sn];
    __shared__ float sUp[UPN];
    __shared__ float red[40];
    int bt = blockIdx.x, tid = threadIdx.x, w = tid >> 5, l = tid & 31;

    for (int i = tid; i < Sn; i += 256) sObj[i] = g_obj[bt * Sn + i];
    if (tid < GUPn) {
        float src = fmaxf((tid + 0.5f) / 4.0f - 0.5f, 0.0f);
        int i0 = min((int)floorf(src), Gn - 1);
        int i1 = min(i0 + 1, Gn - 1);
        float w1 = src - (float)i0;
        for (int j = 0; j < Gn; j++) sWu[tid * Gn + j] = 0.f;
        sWu[tid * Gn + i0] += 1.0f - w1;
        sWu[tid * Gn + i1] += w1;
    }
    __syncthreads();
    // T1[g][v] = sum_h obj[g,h] * Wu[v,h]
    for (int i = tid; i < Gn * GUPn; i += 256) {
        int g = i / GUPn, v = i - g * GUPn;
        float a = 0.f;
        #pragma unroll
        for (int h = 0; h < Gn; h++) a += sObj[g * Gn + h] * sWu[v * Gn + h];
        sT1[g * GUPn + v] = a;
    }
    __syncthreads();
    // up[u][v] = sum_g Wu[u,g] * T1[g][v]
    for (int i = tid; i < UPN; i += 256) {
        int u = i / GUPn, v = i - u * GUPn;
        float a = 0.f;
        #pragma unroll
        for (int g = 0; g < Gn; g++) a += sWu[u * Gn + g] * sT1[g * GUPn + v];
        sUp[i] = a;
    }
    __syncthreads();
    float T = fmaxf(temperature[0], 1.f);
    float mx = -1e30f;
    for (int i = tid; i < UPN; i += 256) mx = fmaxf(mx, sUp[i]);
    mx = warpRedMax(mx);
    if (l == 0) red[w] = mx;
    __syncthreads();
    if (tid == 0) {
        float m2 = red[0];
        for (int i = 1; i < 8; i++) m2 = fmaxf(m2, red[i]);
        red[32] = m2;
    }
    __syncthreads();
    float M = red[32];
    float ls = 0.f, lx = 0.f, ly = 0.f;
    for (int i = tid; i < UPN; i += 256) {
        int u = i / GUPn, v = i - u * GUPn;
        float e = expf((sUp[i] - M) * T);
        ls += e;
        lx += e * ((v + 0.5f) / 56.0f);
        ly += e * ((u + 0.5f) / 56.0f);
    }
    ls = warpRedSum(ls); lx = warpRedSum(lx); ly = warpRedSum(ly);
    if (l == 0) { red[w] = ls; red[8 + w] = lx; red[16 + w] = ly; }
    __syncthreads();
    if (tid == 0) {
        float a = 0.f, b = 0.f, c = 0.f;
        for (int i = 0; i < 8; i++) { a += red[i]; b += red[8 + i]; c += red[16 + i]; }
        float cx0 = b / a, cy0 = c / a;
        g_cxy0[bt * 2] = cx0;
        g_cxy0[bt * 2 + 1] = cy0;
        g_cell[bt * 2] = (int)clampf(cx0 * (float)Gn, 0.f, (float)(Gn - 1));
        g_cell[bt * 2 + 1] = (int)clampf(cy0 * (float)Gn, 0.f, (float)(Gn - 1));
    }
}

// ---------------- K5: pooledX + direct 9-row local gather -------------------
__global__ void __launch_bounds__(768) k_pooled() {
    __shared__ float sp[NHn * Sn];
    int bt = blockIdx.x, tid = threadIdx.x;
    for (int i = tid; i < NHn * Sn; i += 768) sp[i] = g_probs[bt * NHn * Sn + i];
    __syncthreads();
    const float* nb = g_normed + (size_t)bt * Sn * Dn + tid;
    float a0 = 0.f, a1 = 0.f, a2 = 0.f, a3 = 0.f;
    for (int s = 0; s < Sn; s++) {
        float n = nb[(size_t)s * Dn];
        a0 += sp[s] * n;
        a1 += sp[Sn + s] * n;
        a2 += sp[2 * Sn + s] * n;
        a3 += sp[3 * Sn + s] * n;
    }
    float* px = g_pooledX + (size_t)bt * (NHn * Dn);
    px[0 * Dn + tid] = a0;
    px[1 * Dn + tid] = a1;
    px[2 * Dn + tid] = a2;
    px[3 * Dn + tid] = a3;
    // local: direct gather of 9 neighbor token rows (take_along_axis style)
    int cxg = g_cell[bt * 2], cyg = g_cell[bt * 2 + 1];
    float la = 0.f;
    for (int dy = -1; dy <= 1; dy++)
        for (int dx = -1; dx <= 1; dx++) {
            int gy = min(max(cyg + dy, 0), Gn - 1);
            int gx = min(max(cxg + dx, 0), Gn - 1);
            la += nb[(size_t)(gy * Gn + gx) * Dn];
        }
    g_local[bt * Dn + tid] = la / 9.0f;
}

// ---------------- simple GEMM: C[m,n] = bias[n] + dot(Arow, B[n]) -----------
// A and C are selected by scratch IDs (resolved in DEVICE code).
// flags: 1 = gelu(A element), 2 = head-block-diag A (offset by (n/192)*768)
__global__ void __launch_bounds__(256) k_sgemm(int a_id, int lda,
                                               const float* __restrict__ B, int Kfull,
                                               const float* __restrict__ bias,
                                               int c_id, int N, int M,
                                               int Kdim, int flags) {
    const float* A = scratch_ptr(a_id);
    float* C = scratch_ptr(c_id);
    int gw = (blockIdx.x * 256 + threadIdx.x) >> 5;
    int lane = threadIdx.x & 31;
    int nw4 = N >> 2;
    int m = gw / nw4, n0 = (gw - m * nw4) * 4;
    if (m >= M) return;
    const float* arow = A + (size_t)m * lda + ((flags & 2) ? (n0 / 192) * Dn : 0);
    const float* b0 = B + (size_t)n0 * Kfull;
    const float* b1 = b0 + Kfull;
    const float* b2 = b1 + Kfull;
    const float* b3 = b2 + Kfull;
    float acc0 = 0.f, acc1 = 0.f, acc2 = 0.f, acc3 = 0.f;
    for (int k = lane; k < Kdim; k += 32) {
        float a = arow[k];
        if (flags & 1) a = geluf(a);
        acc0 += a * b0[k];
        acc1 += a * b1[k];
        acc2 += a * b2[k];
        acc3 += a * b3[k];
    }
    acc0 = warpRedSum(acc0);
    acc1 = warpRedSum(acc1);
    acc2 = warpRedSum(acc2);
    acc3 = warpRedSum(acc3);
    if (lane == 0) {
        float* cp = C + (size_t)m * N + n0;
        cp[0] = acc0 + bias[n0 + 0];
        cp[1] = acc1 + bias[n0 + 1];
        cp[2] = acc2 + bias[n0 + 2];
        cp[3] = acc3 + bias[n0 + 3];
    }
}

// ---------------- LN(ctx2) + concat local -> A1 ----------------------------
__global__ void __launch_bounds__(768) k_ln_cat(const float* __restrict__ anw,
                                                const float* __restrict__ anb) {
    __shared__ float red[64];
    int bt = blockIdx.x, tid = threadIdx.x, w = tid >> 5, l = tid & 31;
    float x = g_ctx2[bt * Dn + tid];
    float s1 = warpRedSum(x), s2 = warpRedSum(x * x);
    if (l == 0) { red[w] = s1; red[24 + w] = s2; }
    __syncthreads();
    if (tid == 0) {
        float a = 0.f, b = 0.f;
        for (int i = 0; i < 24; i++) { a += red[i]; b += red[24 + i]; }
        red[48] = a; red[49] = b;
    }
    __syncthreads();
    float m = red[48] * (1.f / 768.f);
    float var = red[49] * (1.f / 768.f) - m * m;
    float r = rsqrtf(var + 1e-5f);
    g_A1[bt * (2 * Dn) + tid] = (x - m) * r * anw[tid] + anb[tid];
    g_A1[bt * (2 * Dn) + Dn + tid] = g_local[bt * Dn + tid];
}

// ---------------- delta head: r3 + coarse refine ---------------------------
__global__ void __launch_bounds__(128) k_delta(const float* __restrict__ r3w,
                                               const float* __restrict__ r3b) {
    int bt = blockIdx.x, tid = threadIdx.x;
    float h = geluf(g_h2[bt * 128 + tid]);
    float d0 = h * r3w[tid];
    float d1 = h * r3w[128 + tid];
    __shared__ float rs[8];
    d0 = warpRedSum(d0); d1 = warpRedSum(d1);
    if ((tid & 31) == 0) { rs[(tid >> 5) * 2] = d0; rs[(tid >> 5) * 2 + 1] = d1; }
    __syncthreads();
    if (tid == 0) {
        float s0 = rs[0] + rs[2] + rs[4] + rs[6] + r3b[0];
        float s1 = rs[1] + rs[3] + rs[5] + rs[7] + r3b[1];
        float cx = clampf(g_cxy0[bt * 2] + 0.3f * tanhf(s0), 0.f, 1.f);
        float cy = clampf(g_cxy0[bt * 2 + 1] + 0.3f * tanhf(s1), 0.f, 1.f);
        g_cxy0[bt * 2] = cx;
        g_cxy0[bt * 2 + 1] = cy;
    }
}

// ---------------- temporal convs + box assembly ----------------------------
__global__ void __launch_bounds__(64) k_conv_final(const float* __restrict__ tc1w,
                                                   const float* __restrict__ tc1b,
                                                   const float* __restrict__ tc2w,
                                                   const float* __restrict__ tc2b,
                                                   const float* __restrict__ fbwh,
                                                   float* __restrict__ out) {
    __shared__ float seq[2][16], t1s[32][16], tds[2][16];
    int b = blockIdx.x, tid = threadIdx.x;
    if (tid < 32) {
        int i = tid >> 4, t = tid & 15;
        seq[i][t] = g_cxy0[(b * 16 + t) * 2 + i];
    }
    __syncthreads();
    if (tid < 32) {
        int c = tid;
        for (int t = 0; t < 16; t++) {
            float acc = tc1b[c];
            #pragma unroll
            for (int i = 0; i < 2; i++)
                #pragma unroll
                for (int k = 0; k < 5; k++) {
                    int tt = t + k - 2;
                    if (tt >= 0 && tt < 16) acc += seq[i][tt] * tc1w[c * 10 + i * 5 + k];
                }
            t1s[c][t] = geluf(acc);
        }
    }
    __syncthreads();
    if (tid < 32) {
        int o = tid >> 4, t = tid & 15;
        float acc = tc2b[o];
        for (int c = 0; c < 32; c++)
            #pragma unroll
            for (int k = 0; k < 5; k++) {
                int tt = t + k - 2;
                if (tt >= 0 && tt < 16) acc += t1s[c][tt] * tc2w[o * 160 + c * 5 + k];
            }
        tds[o][t] = acc;
    }
    __syncthreads();
    if (tid < 16) {
        int t = tid, bt = b * 16 + t;
        const float minsz = 1.0f / 14.0f;
        float cx = clampf(g_cxy0[bt * 2] + 0.12f * tanhf(tds[0][t]), 0.f, 1.f);
        float cy = clampf(g_cxy0[bt * 2 + 1] + 0.12f * tanhf(tds[1][t]), 0.f, 1.f);
        float w = clampf(fbwh[0], minsz, 1.f);
        float hh = clampf(fbwh[1], minsz, 1.f);
        float x1 = clampf(cx - 0.5f * w, 0.f, 1.f);
        float y1 = clampf(cy - 0.5f * hh, 0.f, 1.f);
        float x2 = clampf(cx + 0.5f * w, 0.f, 1.f);
        float y2 = clampf(cy + 0.5f * hh, 0.f, 1.f);
        x2 = clampf(fmaxf(x2, x1 + minsz), 0.f, 1.f);
        y2 = clampf(fmaxf(y2, y1 + minsz), 0.f, 1.f);
        out[bt * 4 + 0] = x1;
        out[bt * 4 + 1] = y1;
        out[bt * 4 + 2] = x2;
        out[bt * 4 + 3] = y2;
    }
}

// ---------------- launch --------------------------------------------------
extern "C" void kernel_launch(void* const* d_in, const int* in_sizes, int n_in,
                              void* d_out, int out_size) {
    const float* tokens = (const float*)d_in[0];
    const float* fbwh   = (const float*)d_in[2];
    const float* ln_w   = (const float*)d_in[3];
    const float* ln_b   = (const float*)d_in[4];
    const float* query  = (const float*)d_in[5];
    const float* ipw    = (const float*)d_in[6];
    const float* ipb    = (const float*)d_in[7];
    const float* out_w  = (const float*)d_in[8];
    const float* out_b  = (const float*)d_in[9];
    const float* an_w   = (const float*)d_in[10];
    const float* an_b   = (const float*)d_in[11];
    const float* obj_w  = (const float*)d_in[12];
    const float* obj_b  = (const float*)d_in[13];
    const float* temp   = (const float*)d_in[14];
    const float* r1_w   = (const float*)d_in[15];
    const float* r1_b   = (const float*)d_in[16];
    const float* r2_w   = (const float*)d_in[17];
    const float* r2_b   = (const float*)d_in[18];
    const float* r3_w   = (const float*)d_in[19];
    const float* r3_b   = (const float*)d_in[20];
    const float* tc1_w  = (const float*)d_in[21];
    const float* tc1_b  = (const float*)d_in[22];
    const float* tc2_w  = (const float*)d_in[23];
    const float* tc2_b  = (const float*)d_in[24];
    float* out = (float*)d_out;

    k_prep_qh<<<Dn, 128>>>(query, ipw, ipb);
    k_prep_wk2<<<NHn, 768>>>(ipw, ipb);

    k_ln_score<<<BT * Sn, 768>>>(tokens, ln_w, ln_b, obj_w, obj_b);
    k_softmax<<<BT, 128>>>();
    k_spatial<<<BT, 256>>>(temp);
    k_pooled<<<BT, 768>>>();

    // G1: ctx = pooledX (head-block-diag, id 0) @ Wv^T + bv  -> g_ctx (id 1)
    k_sgemm<<<6144, 256>>>(0, NHn * Dn, ipw + (size_t)2 * Dn * Dn, Dn,
                           ipb + 2 * Dn, 1, Dn, BT, Dn, 2);
    // G2: ctx2 = ctx (id 1) @ out_w^T + out_b -> g_ctx2 (id 2)
    k_sgemm<<<6144, 256>>>(1, Dn, out_w, Dn, out_b, 2, Dn, BT, Dn, 0);

    k_ln_cat<<<BT, 768>>>(an_w, an_b);

    // G3: h1_pre = A1 (id 3) @ r1_w^T + r1_b -> g_h1 (id 4)
    k_sgemm<<<2048, 256>>>(3, 2 * Dn, r1_w, 2 * Dn, r1_b, 4, 256, BT, 2 * Dn, 0);
    // G4: h2_pre = gelu(h1_pre) (id 4) @ r2_w^T + r2_b -> g_h2 (id 5)
    k_sgemm<<<1024, 256>>>(4, 256, r2_w, 256, r2_b, 5, 128, BT, 256, 1);

    k_delta<<<BT, 128>>>(r3_w, r3_b);
    k_conv_final<<<Bn, 64>>>(tc1_w, tc1_b, tc2_w, tc2_b, fbwh, out);
}

// round 12
// speedup vs baseline: 1.6507x; 1.6507x over previous
#include <cuda_runtime.h>
#include <math.h>

// ---------------- problem constants ----------------
constexpr int Bn = 16, Tn = 16, Sn = 196, Dn = 768;
constexpr int NHn = 4, Gn = 14, GUPn = 56, UPN = GUPn * GUPn;
constexpr int BT = Bn * Tn;      // 256
constexpr float RSQRT_DH = 0.07216878364870323f;  // 1/sqrt(192)

#define DEV static __device__ __forceinline__

// ---------------- scratch (device globals; no allocations allowed) ----------
__device__ float g_qh[Dn];
__device__ float g_wk[NHn * Dn];
__device__ float g_sbias[NHn];
__device__ float g_cxy0[BT * 2];
__device__ float g_pooledX[BT * NHn * Dn];
__device__ float g_local[BT * Dn];
__device__ float g_ctx[BT * Dn];
__device__ float g_ctx2[BT * Dn];
__device__ float g_A1[BT * 2 * Dn];
__device__ float g_h1[BT * 256];
__device__ float g_h2[BT * 128];

// Scratch selector: device-side resolution of scratch buffers.
// NEVER pass __device__ globals as kernel args from host code — on GB300
// (ATS/HMM) the host shadow address is dereferenceable by the GPU and reads
// silently return zeros instead of faulting.
DEV float* scratch_ptr(int id) {
    switch (id) {
        case 0: return g_pooledX;
        case 1: return g_ctx;
        case 2: return g_ctx2;
        case 3: return g_A1;
        case 4: return g_h1;
        case 5: return g_h2;
    }
    return nullptr;
}

// ---------------- helpers ----------------
DEV float warpRedSum(float v) {
    #pragma unroll
    for (int o = 16; o; o >>= 1) v += __shfl_xor_sync(0xffffffffu, v, o);
    return v;
}
DEV float warpRedMax(float v) {
    #pragma unroll
    for (int o = 16; o; o >>= 1) v = fmaxf(v, __shfl_xor_sync(0xffffffffu, v, o));
    return v;
}
// red must hold >= 96 floats
DEV float blockRedMax(float v, float* red) {
    int tid = threadIdx.x, w = tid >> 5, l = tid & 31, nw = blockDim.x >> 5;
    v = warpRedMax(v);
    if (l == 0) red[w] = v;
    __syncthreads();
    if (tid == 0) { float m = red[0]; for (int i = 1; i < nw; i++) m = fmaxf(m, red[i]); red[80] = m; }
    __syncthreads();
    v = red[80];
    __syncthreads();
    return v;
}
DEV void blockRed3(float& a, float& b, float& c, float* red) {
    int tid = threadIdx.x, w = tid >> 5, l = tid & 31, nw = blockDim.x >> 5;
    a = warpRedSum(a); b = warpRedSum(b); c = warpRedSum(c);
    if (l == 0) { red[w * 3] = a; red[w * 3 + 1] = b; red[w * 3 + 2] = c; }
    __syncthreads();
    if (tid == 0) {
        float sa = 0.f, sb = 0.f, sc = 0.f;
        for (int i = 0; i < nw; i++) { sa += red[i * 3]; sb += red[i * 3 + 1]; sc += red[i * 3 + 2]; }
        red[80] = sa; red[81] = sb; red[82] = sc;
    }
    __syncthreads();
    a = red[80]; b = red[81]; c = red[82];
    __syncthreads();
}
DEV void blockRed2(float& a, float& b, float* red) {
    int tid = threadIdx.x, w = tid >> 5, l = tid & 31, nw = blockDim.x >> 5;
    a = warpRedSum(a); b = warpRedSum(b);
    if (l == 0) { red[w * 2] = a; red[w * 2 + 1] = b; }
    __syncthreads();
    if (tid == 0) {
        float sa = 0.f, sb = 0.f;
        for (int i = 0; i < nw; i++) { sa += red[i * 2]; sb += red[i * 2 + 1]; }
        red[80] = sa; red[81] = sb;
    }
    __syncthreads();
    a = red[80]; b = red[81];
    __syncthreads();
}
DEV float geluf(float x) { return 0.5f * x * (1.0f + erff(x * 0.70710678118654752f)); }
DEV float clampf(float x, float lo, float hi) { return fminf(fmaxf(x, lo), hi); }

// ---------------- K1a: qh[j] = query . Wq[j] + bq[j] ------------------------
__global__ void __launch_bounds__(128) k_prep_qh(const float* __restrict__ query,
                                                 const float* __restrict__ ipw,
                                                 const float* __restrict__ ipb) {
    int j = blockIdx.x, tid = threadIdx.x;
    float p = 0.f;
    const float* row = ipw + (size_t)j * Dn;
    for (int k = tid; k < Dn; k += 128) p += query[k] * row[k];
    __shared__ float r4[4];
    p = warpRedSum(p);
    if ((tid & 31) == 0) r4[tid >> 5] = p;
    __syncthreads();
    if (tid == 0) g_qh[j] = r4[0] + r4[1] + r4[2] + r4[3] + ipb[j];
}

// ---------------- K1b: wk_eff[h][d] = sum_j qh[h,j] * Wk[h*192+j][d] --------
__global__ void __launch_bounds__(768) k_prep_wk2(const float* __restrict__ ipw,
                                                  const float* __restrict__ ipb) {
    int h = blockIdx.x, tid = threadIdx.x;
    __shared__ float qs[192];
    if (tid < 192) qs[tid] = g_qh[h * 192 + tid];
    __syncthreads();
    float acc = 0.f;
    const float* base = ipw + (size_t)(Dn + h * 192) * Dn;
    for (int j = 0; j < 192; j++) acc += qs[j] * base[(size_t)j * Dn + tid];
    g_wk[h * Dn + tid] = acc;
    if (tid == 0) {
        float s = 0.f;
        for (int j = 0; j < 192; j++) s += qs[j] * ipb[Dn + h * 192 + j];
        g_sbias[h] = s;
    }
}

// ---------------- K2: fused big pass, one block per (b,t) -------------------
__global__ void __launch_bounds__(768) k_main(const float* __restrict__ tokens,
                                              const float* __restrict__ ln_w,
                                              const float* __restrict__ ln_b,
                                              const float* __restrict__ obj_w,
                                              const float* __restrict__ obj_b,
                                              const float* __restrict__ temperature) {
    __shared__ float s_lnw[Dn], s_lnb[Dn], s_objw[Dn];
    __shared__ float s_wk[NHn * Dn];
    __shared__ float s_sbias[NHn];
    __shared__ float s_m[Sn], s_r[Sn];
    __shared__ float s_sc[NHn * Sn];   // scores -> probs
    __shared__ float s_obj[Sn];
    __shared__ float s_up[UPN];
    __shared__ float s_lw[Sn];
    __shared__ int s_i0[GUPn], s_i1[GUPn];
    __shared__ float s_w0[GUPn], s_w1[GUPn];
    __shared__ float s_red[96];

    const int bt = blockIdx.x;
    const int tid = threadIdx.x;
    const int wid = tid >> 5, lane = tid & 31;
    const float* tok = tokens + (size_t)bt * Sn * Dn;

    // load constants
    s_lnw[tid] = ln_w[tid];
    s_lnb[tid] = ln_b[tid];
    s_objw[tid] = obj_w[tid];
    #pragma unroll
    for (int h = 0; h < NHn; h++) s_wk[h * Dn + tid] = g_wk[h * Dn + tid];
    if (tid < NHn) s_sbias[tid] = g_sbias[tid];
    __syncthreads();

    // ---- phase 1: warp-per-token LN + scores + obj ----
    for (int s = wid; s < Sn; s += 24) {
        const float* xp = tok + (size_t)s * Dn;
        float xv[24];
        float sum = 0.f, sq = 0.f;
        #pragma unroll
        for (int i = 0; i < 24; i++) {
            float v = xp[lane + 32 * i];
            xv[i] = v; sum += v; sq += v * v;
        }
        sum = warpRedSum(sum);
        sq = warpRedSum(sq);
        float m = sum * (1.f / 768.f);
        float var = sq * (1.f / 768.f) - m * m;
        float rstd = rsqrtf(var + 1e-5f);
        float d0 = 0.f, d1 = 0.f, d2 = 0.f, d3 = 0.f, dob = 0.f;
        #pragma unroll
        for (int i = 0; i < 24; i++) {
            int d = lane + 32 * i;
            float n = (xv[i] - m) * rstd * s_lnw[d] + s_lnb[d];
            d0 += n * s_wk[d];
            d1 += n * s_wk[Dn + d];
            d2 += n * s_wk[2 * Dn + d];
            d3 += n * s_wk[3 * Dn + d];
            dob += n * s_objw[d];
        }
        d0 = warpRedSum(d0); d1 = warpRedSum(d1);
        d2 = warpRedSum(d2); d3 = warpRedSum(d3);
        dob = warpRedSum(dob);
        if (lane == 0) {
            s_sc[0 * Sn + s] = (d0 + s_sbias[0]) * RSQRT_DH;
            s_sc[1 * Sn + s] = (d1 + s_sbias[1]) * RSQRT_DH;
            s_sc[2 * Sn + s] = (d2 + s_sbias[2]) * RSQRT_DH;
            s_sc[3 * Sn + s] = (d3 + s_sbias[3]) * RSQRT_DH;
            s_obj[s] = dob + obj_b[0];
            s_m[s] = m; s_r[s] = rstd;
        }
    }
    __syncthreads();

    // ---- phase 2a: per-head softmax (warps 0..3); others: tables, zero lw --
    if (wid < NHn) {
        int h = wid;
        float mx = -1e30f;
        for (int s = lane; s < Sn; s += 32) mx = fmaxf(mx, s_sc[h * Sn + s]);
        mx = warpRedMax(mx);
        float sum = 0.f;
        for (int s = lane; s < Sn; s += 32) {
            float e = expf(s_sc[h * Sn + s] - mx);
            s_sc[h * Sn + s] = e; sum += e;
        }
        sum = warpRedSum(sum);
        float inv = 1.f / sum;
        for (int s = lane; s < Sn; s += 32) s_sc[h * Sn + s] *= inv;
    } else if (tid >= 128 && tid < 128 + GUPn) {
        int u = tid - 128;
        float src = fmaxf((u + 0.5f) * 0.25f - 0.5f, 0.f);
        int i0 = min((int)floorf(src), Gn - 1);
        int i1 = min(i0 + 1, Gn - 1);
        float w1 = src - (float)i0;
        s_i0[u] = i0; s_i1[u] = i1; s_w0[u] = 1.f - w1; s_w1[u] = w1;
    } else if (tid >= 192 && tid < 192 + Sn) {
        s_lw[tid - 192] = 0.f;
    }
    __syncthreads();

    // ---- phase 2b: bilinear upsample 14->56 ----
    for (int idx = tid; idx < UPN; idx += 768) {
        int u = idx / GUPn, v = idx - u * GUPn;
        int a0 = s_i0[u], a1 = s_i1[u], b0 = s_i0[v], b1 = s_i1[v];
        float r0 = s_w0[v] * s_obj[a0 * Gn + b0] + s_w1[v] * s_obj[a0 * Gn + b1];
        float r1 = s_w0[v] * s_obj[a1 * Gn + b0] + s_w1[v] * s_obj[a1 * Gn + b1];
        s_up[idx] = s_w0[u] * r0 + s_w1[u] * r1;
    }
    __syncthreads();

    // ---- phase 2c: spatial softmax + expected coords ----
    float Ttemp = fmaxf(temperature[0], 1.f);
    float lmax = -1e30f;
    for (int idx = tid; idx < UPN; idx += 768) lmax = fmaxf(lmax, s_up[idx]);
    float M = blockRedMax(lmax, s_red);
    float ls = 0.f, lcx = 0.f, lcy = 0.f;
    for (int idx = tid; idx < UPN; idx += 768) {
        int u = idx / GUPn, v = idx - u * GUPn;
        float e = expf((s_up[idx] - M) * Ttemp);
        ls += e;
        lcx += e * ((v + 0.5f) * (1.f / GUPn));
        lcy += e * ((u + 0.5f) * (1.f / GUPn));
    }
    blockRed3(ls, lcx, lcy, s_red);
    float cx0 = lcx / ls, cy0 = lcy / ls;
    if (tid == 0) {
        g_cxy0[bt * 2] = cx0;
        g_cxy0[bt * 2 + 1] = cy0;
        int cxg = (int)clampf(cx0 * (float)Gn, 0.f, (float)(Gn - 1));
        int cyg = (int)clampf(cy0 * (float)Gn, 0.f, (float)(Gn - 1));
        for (int dy = -1; dy <= 1; dy++)
            for (int dx = -1; dx <= 1; dx++) {
                int gy = min(max(cyg + dy, 0), Gn - 1);
                int gx = min(max(cxg + dx, 0), Gn - 1);
                s_lw[gy * Gn + gx] += 1.f / 9.f;
            }
    }
    __syncthreads();

    // ---- phase 3: d-parallel resweep (L2-hot) -> pooledX + local ----
    {
        int d = tid;
        float a0 = 0.f, a1 = 0.f, a2 = 0.f, a3 = 0.f, la = 0.f;
        float lw = s_lnw[d], lb = s_lnb[d];
        const float* xp = tok + d;
        for (int s = 0; s < Sn; s++) {
            float n = (xp[(size_t)s * Dn] - s_m[s]) * s_r[s] * lw + lb;
            a0 += s_sc[0 * Sn + s] * n;
            a1 += s_sc[1 * Sn + s] * n;
            a2 += s_sc[2 * Sn + s] * n;
            a3 += s_sc[3 * Sn + s] * n;
            la += s_lw[s] * n;
        }
        float* px = g_pooledX + (size_t)bt * (NHn * Dn);
        px[0 * Dn + d] = a0;
        px[1 * Dn + d] = a1;
        px[2 * Dn + d] = a2;
        px[3 * Dn + d] = a3;
        g_local[bt * Dn + d] = la;
    }
}

// ---------------- tiled GEMM: C[m,n] = bias[n] + sum_k A[m,k]*B[n,k] --------
// 64x64 block tile, BK=16, 4x4 micro-tile, 256 threads, no k-split.
// A and C resolved device-side by scratch id.
// flags: 1 = gelu(A element), 2 = head-block-diag A (offset (n0/192)*768)
__global__ void __launch_bounds__(256) k_tgemm(int a_id, int lda,
                                               const float* __restrict__ B, int ldb,
                                               const float* __restrict__ bias,
                                               int c_id, int N, int Kdim, int flags) {
    __shared__ float As[16][68], Bs[16][68];
    const float* A = scratch_ptr(a_id);
    float* C = scratch_ptr(c_id);
    int tid = threadIdx.x;
    int m0 = blockIdx.y * 64, n0 = blockIdx.x * 64;
    int aoff = (flags & 2) ? (n0 / 192) * Dn : 0;
    int tx = tid & 15, ty = tid >> 4;   // 16x16 thread grid
    float acc[4][4] = {};
    for (int k0 = 0; k0 < Kdim; k0 += 16) {
        #pragma unroll
        for (int i = 0; i < 4; i++) {
            int idx = tid + i * 256;            // 0..1023
            int mm = idx >> 4, kk = idx & 15;   // 64 rows x 16 cols
            float a = A[(size_t)(m0 + mm) * lda + aoff + k0 + kk];
            if (flags & 1) a = geluf(a);
            As[kk][mm] = a;
            Bs[kk][mm] = B[(size_t)(n0 + mm) * ldb + k0 + kk];
        }
        __syncthreads();
        #pragma unroll
        for (int kk = 0; kk < 16; kk++) {
            float av[4], bv[4];
            #pragma unroll
            for (int i = 0; i < 4; i++) { av[i] = As[kk][ty * 4 + i]; bv[i] = Bs[kk][tx * 4 + i]; }
            #pragma unroll
            for (int i = 0; i < 4; i++)
                #pragma unroll
                for (int j = 0; j < 4; j++)
                    acc[i][j] += av[i] * bv[j];
        }
        __syncthreads();
    }
    #pragma unroll
    for (int i = 0; i < 4; i++)
        #pragma unroll
        for (int j = 0; j < 4; j++)
            C[(size_t)(m0 + ty * 4 + i) * N + n0 + tx * 4 + j] = acc[i][j] + bias[n0 + tx * 4 + j];
}

// ---------------- LN(ctx2) + concat local -> A1 ----------------------------
__global__ void __launch_bounds__(768) k_ln_cat(const float* __restrict__ anw,
                                                const float* __restrict__ anb) {
    __shared__ float red[96];
    int bt = blockIdx.x, tid = threadIdx.x;
    float x = g_ctx2[bt * Dn + tid];
    float s = x, sq = x * x;
    blockRed2(s, sq, red);
    float m = s * (1.f / 768.f);
    float var = sq * (1.f / 768.f) - m * m;
    float r = rsqrtf(var + 1e-5f);
    g_A1[bt * (2 * Dn) + tid] = (x - m) * r * anw[tid] + anb[tid];
    g_A1[bt * (2 * Dn) + Dn + tid] = g_local[bt * Dn + tid];
}

// ---------------- delta head: r3 + coarse refine ---------------------------
__global__ void __launch_bounds__(128) k_delta(const float* __restrict__ r3w,
                                               const float* __restrict__ r3b) {
    int bt = blockIdx.x, tid = threadIdx.x;
    float h = geluf(g_h2[bt * 128 + tid]);
    float d0 = h * r3w[tid];
    float d1 = h * r3w[128 + tid];
    __shared__ float rs[8];
    d0 = warpRedSum(d0); d1 = warpRedSum(d1);
    if ((tid & 31) == 0) { rs[(tid >> 5) * 2] = d0; rs[(tid >> 5) * 2 + 1] = d1; }
    __syncthreads();
    if (tid == 0) {
        float s0 = rs[0] + rs[2] + rs[4] + rs[6] + r3b[0];
        float s1 = rs[1] + rs[3] + rs[5] + rs[7] + r3b[1];
        float cx = clampf(g_cxy0[bt * 2] + 0.3f * tanhf(s0), 0.f, 1.f);
        float cy = clampf(g_cxy0[bt * 2 + 1] + 0.3f * tanhf(s1), 0.f, 1.f);
        g_cxy0[bt * 2] = cx;
        g_cxy0[bt * 2 + 1] = cy;
    }
}

// ---------------- temporal convs + box assembly ----------------------------
__global__ void __launch_bounds__(64) k_conv_final(const float* __restrict__ tc1w,
                                                   const float* __restrict__ tc1b,
                                                   const float* __restrict__ tc2w,
                                                   const float* __restrict__ tc2b,
                                                   const float* __restrict__ fbwh,
                                                   float* __restrict__ out) {
    __shared__ float seq[2][16], t1s[32][16], tds[2][16];
    int b = blockIdx.x, tid = threadIdx.x;
    if (tid < 32) {
        int i = tid >> 4, t = tid & 15;
        seq[i][t] = g_cxy0[(b * 16 + t) * 2 + i];
    }
    __syncthreads();
    if (tid < 32) {
        int c = tid;
        for (int t = 0; t < 16; t++) {
            float acc = tc1b[c];
            #pragma unroll
            for (int i = 0; i < 2; i++)
                #pragma unroll
                for (int k = 0; k < 5; k++) {
                    int tt = t + k - 2;
                    if (tt >= 0 && tt < 16) acc += seq[i][tt] * tc1w[c * 10 + i * 5 + k];
                }
            t1s[c][t] = geluf(acc);
        }
    }
    __syncthreads();
    if (tid < 32) {
        int o = tid >> 4, t = tid & 15;
        float acc = tc2b[o];
        for (int c = 0; c < 32; c++)
            #pragma unroll
            for (int k = 0; k < 5; k++) {
                int tt = t + k - 2;
                if (tt >= 0 && tt < 16) acc += t1s[c][tt] * tc2w[o * 160 + c * 5 + k];
            }
        tds[o][t] = acc;
    }
    __syncthreads();
    if (tid < 16) {
        int t = tid, bt = b * 16 + t;
        const float minsz = 1.0f / 14.0f;
        float cx = clampf(g_cxy0[bt * 2] + 0.12f * tanhf(tds[0][t]), 0.f, 1.f);
        float cy = clampf(g_cxy0[bt * 2 + 1] + 0.12f * tanhf(tds[1][t]), 0.f, 1.f);
        float w = clampf(fbwh[0], minsz, 1.f);
        float hh = clampf(fbwh[1], minsz, 1.f);
        float x1 = clampf(cx - 0.5f * w, 0.f, 1.f);
        float y1 = clampf(cy - 0.5f * hh, 0.f, 1.f);
        float x2 = clampf(cx + 0.5f * w, 0.f, 1.f);
        float y2 = clampf(cy + 0.5f * hh, 0.f, 1.f);
        x2 = clampf(fmaxf(x2, x1 + minsz), 0.f, 1.f);
        y2 = clampf(fmaxf(y2, y1 + minsz), 0.f, 1.f);
        out[bt * 4 + 0] = x1;
        out[bt * 4 + 1] = y1;
        out[bt * 4 + 2] = x2;
        out[bt * 4 + 3] = y2;
    }
}

// ---------------- launch --------------------------------------------------
extern "C" void kernel_launch(void* const* d_in, const int* in_sizes, int n_in,
                              void* d_out, int out_size) {
    const float* tokens = (const float*)d_in[0];
    const float* fbwh   = (const float*)d_in[2];
    const float* ln_w   = (const float*)d_in[3];
    const float* ln_b   = (const float*)d_in[4];
    const float* query  = (const float*)d_in[5];
    const float* ipw    = (const float*)d_in[6];
    const float* ipb    = (const float*)d_in[7];
    const float* out_w  = (const float*)d_in[8];
    const float* out_b  = (const float*)d_in[9];
    const float* an_w   = (const float*)d_in[10];
    const float* an_b   = (const float*)d_in[11];
    const float* obj_w  = (const float*)d_in[12];
    const float* obj_b  = (const float*)d_in[13];
    const float* temp   = (const float*)d_in[14];
    const float* r1_w   = (const float*)d_in[15];
    const float* r1_b   = (const float*)d_in[16];
    const float* r2_w   = (const float*)d_in[17];
    const float* r2_b   = (const float*)d_in[18];
    const float* r3_w   = (const float*)d_in[19];
    const float* r3_b   = (const float*)d_in[20];
    const float* tc1_w  = (const float*)d_in[21];
    const float* tc1_b  = (const float*)d_in[22];
    const float* tc2_w  = (const float*)d_in[23];
    const float* tc2_b  = (const float*)d_in[24];
    float* out = (float*)d_out;

    k_prep_qh<<<Dn, 128>>>(query, ipw, ipb);
    k_prep_wk2<<<NHn, 768>>>(ipw, ipb);

    // fused LN + scores + softmax + spatial + pooled/local
    k_main<<<BT, 768>>>(tokens, ln_w, ln_b, obj_w, obj_b, temp);

    // G1: ctx = pooledX (head-block-diag, id 0) @ Wv^T + bv -> g_ctx (id 1)
    k_tgemm<<<dim3(12, 4), 256>>>(0, NHn * Dn, ipw + (size_t)2 * Dn * Dn, Dn,
                                  ipb + 2 * Dn, 1, Dn, Dn, 2);
    // G2: ctx2 = ctx (id 1) @ out_w^T + out_b -> g_ctx2 (id 2)
    k_tgemm<<<dim3(12, 4), 256>>>(1, Dn, out_w, Dn, out_b, 2, Dn, Dn, 0);

    k_ln_cat<<<BT, 768>>>(an_w, an_b);

    // G3: h1_pre = A1 (id 3) @ r1_w^T + r1_b -> g_h1 (id 4)
    k_tgemm<<<dim3(4, 4), 256>>>(3, 2 * Dn, r1_w, 2 * Dn, r1_b, 4, 256, 2 * Dn, 0);
    // G4: h2_pre = gelu(h1_pre) (id 4) @ r2_w^T + r2_b -> g_h2 (id 5)
    k_tgemm<<<dim3(2, 4), 256>>>(4, 256, r2_w, 256, r2_b, 5, 128, 256, 1);

    k_delta<<<BT, 128>>>(r3_w, r3_b);
    k_conv_final<<<Bn, 64>>>(tc1_w, tc1_b, tc2_w, tc2_b, fbwh, out);
}

// round 15
// speedup vs baseline: 2.6363x; 1.5971x over previous
#include <cuda_runtime.h>
#include <math.h>

// ---------------- problem constants ----------------
constexpr int Bn = 16, Tn = 16, Sn = 196, Dn = 768;
constexpr int NHn = 4, Gn = 14, GUPn = 56, UPN = GUPn * GUPn;
constexpr int BT = Bn * Tn;      // 256
constexpr float RSQRT_DH = 0.07216878364870323f;  // 1/sqrt(192)

#define DEV static __device__ __forceinline__

// ---------------- scratch (device globals; no allocations allowed) ----------
__device__ float g_qh[Dn];
__device__ float g_wk[NHn * Dn];
__device__ float g_sbias[NHn];
__device__ float g_cxy0[BT * 2];
__device__ float g_pooledX[BT * NHn * Dn];
__device__ float g_local[BT * Dn];
__device__ float g_ctx[BT * Dn];
__device__ float g_ctx2[BT * Dn];
__device__ float g_A1[BT * 2 * Dn];
__device__ float g_h1[BT * 256];
__device__ float g_h2[BT * 128];
__device__ float g_part[8 * BT * Dn];   // k-split partials (max 8 slices x 256x768)

// Scratch selector: device-side resolution of scratch buffers.
// NEVER pass __device__ globals as kernel args from host code — on GB300
// (ATS/HMM) the host shadow address is dereferenceable by the GPU and reads
// silently return zeros instead of faulting.
DEV float* scratch_ptr(int id) {
    switch (id) {
        case 0: return g_pooledX;
        case 1: return g_ctx;
        case 2: return g_ctx2;
        case 3: return g_A1;
        case 4: return g_h1;
        case 5: return g_h2;
        case 6: return g_part;
    }
    return nullptr;
}

// ---------------- helpers ----------------
DEV float warpRedSum(float v) {
    #pragma unroll
    for (int o = 16; o; o >>= 1) v += __shfl_xor_sync(0xffffffffu, v, o);
    return v;
}
DEV float warpRedMax(float v) {
    #pragma unroll
    for (int o = 16; o; o >>= 1) v = fmaxf(v, __shfl_xor_sync(0xffffffffu, v, o));
    return v;
}
// red must hold >= 96 floats
DEV float blockRedMax(float v, float* red) {
    int tid = threadIdx.x, w = tid >> 5, l = tid & 31, nw = blockDim.x >> 5;
    v = warpRedMax(v);
    if (l == 0) red[w] = v;
    __syncthreads();
    if (tid == 0) { float m = red[0]; for (int i = 1; i < nw; i++) m = fmaxf(m, red[i]); red[80] = m; }
    __syncthreads();
    v = red[80];
    __syncthreads();
    return v;
}
DEV void blockRed3(float& a, float& b, float& c, float* red) {
    int tid = threadIdx.x, w = tid >> 5, l = tid & 31, nw = blockDim.x >> 5;
    a = warpRedSum(a); b = warpRedSum(b); c = warpRedSum(c);
    if (l == 0) { red[w * 3] = a; red[w * 3 + 1] = b; red[w * 3 + 2] = c; }
    __syncthreads();
    if (tid == 0) {
        float sa = 0.f, sb = 0.f, sc = 0.f;
        for (int i = 0; i < nw; i++) { sa += red[i * 3]; sb += red[i * 3 + 1]; sc += red[i * 3 + 2]; }
        red[80] = sa; red[81] = sb; red[82] = sc;
    }
    __syncthreads();
    a = red[80]; b = red[81]; c = red[82];
    __syncthreads();
}
DEV void blockRed2(float& a, float& b, float* red) {
    int tid = threadIdx.x, w = tid >> 5, l = tid & 31, nw = blockDim.x >> 5;
    a = warpRedSum(a); b = warpRedSum(b);
    if (l == 0) { red[w * 2] = a; red[w * 2 + 1] = b; }
    __syncthreads();
    if (tid == 0) {
        float sa = 0.f, sb = 0.f;
        for (int i = 0; i < nw; i++) { sa += red[i * 2]; sb += red[i * 2 + 1]; }
        red[80] = sa; red[81] = sb;
    }
    __syncthreads();
    a = red[80]; b = red[81];
    __syncthreads();
}
DEV float geluf(float x) { return 0.5f * x * (1.0f + erff(x * 0.70710678118654752f)); }
DEV float clampf(float x, float lo, float hi) { return fminf(fmaxf(x, lo), hi); }

// ---------------- K1a: qh[j] = query . Wq[j] + bq[j] ------------------------
__global__ void __launch_bounds__(128) k_prep_qh(const float* __restrict__ query,
                                                 const float* __restrict__ ipw,
                                                 const float* __restrict__ ipb) {
    int j = blockIdx.x, tid = threadIdx.x;
    float p = 0.f;
    const float* row = ipw + (size_t)j * Dn;
    for (int k = tid; k < Dn; k += 128) p += query[k] * row[k];
    __shared__ float r4[4];
    p = warpRedSum(p);
    if ((tid & 31) == 0) r4[tid >> 5] = p;
    __syncthreads();
    if (tid == 0) g_qh[j] = r4[0] + r4[1] + r4[2] + r4[3] + ipb[j];
}

// ---------------- K1b: wk_eff[h][d] = sum_j qh[h,j] * Wk[h*192+j][d] --------
__global__ void __launch_bounds__(768) k_prep_wk2(const float* __restrict__ ipw,
                                                  const float* __restrict__ ipb) {
    int h = blockIdx.x, tid = threadIdx.x;
    __shared__ float qs[192];
    if (tid < 192) qs[tid] = g_qh[h * 192 + tid];
    __syncthreads();
    float acc = 0.f;
    const float* base = ipw + (size_t)(Dn + h * 192) * Dn;
    for (int j = 0; j < 192; j++) acc += qs[j] * base[(size_t)j * Dn + tid];
    g_wk[h * Dn + tid] = acc;
    if (tid == 0) {
        float s = 0.f;
        for (int j = 0; j < 192; j++) s += qs[j] * ipb[Dn + h * 192 + j];
        g_sbias[h] = s;
    }
}

// ---------------- K2: fused big pass, one block per (b,t) -------------------
__global__ void __launch_bounds__(768) k_main(const float* __restrict__ tokens,
                                              const float* __restrict__ ln_w,
                                              const float* __restrict__ ln_b,
                                              const float* __restrict__ obj_w,
                                              const float* __restrict__ obj_b,
                                              const float* __restrict__ temperature) {
    __shared__ float s_lnw[Dn], s_lnb[Dn], s_objw[Dn];
    __shared__ float s_wk[NHn * Dn];
    __shared__ float s_sbias[NHn];
    __shared__ float s_m[Sn], s_r[Sn];
    __shared__ float s_sc[NHn * Sn];   // scores -> probs
    __shared__ float s_obj[Sn];
    __shared__ float s_up[UPN];
    __shared__ float s_lw[Sn];
    __shared__ int s_i0[GUPn], s_i1[GUPn];
    __shared__ float s_w0[GUPn], s_w1[GUPn];
    __shared__ float s_red[96];

    const int bt = blockIdx.x;
    const int tid = threadIdx.x;
    const int wid = tid >> 5, lane = tid & 31;
    const float* tok = tokens + (size_t)bt * Sn * Dn;

    // load constants
    s_lnw[tid] = ln_w[tid];
    s_lnb[tid] = ln_b[tid];
    s_objw[tid] = obj_w[tid];
    #pragma unroll
    for (int h = 0; h < NHn; h++) s_wk[h * Dn + tid] = g_wk[h * Dn + tid];
    if (tid < NHn) s_sbias[tid] = g_sbias[tid];
    __syncthreads();

    // ---- phase 1: warp-per-token LN + scores + obj ----
    for (int s = wid; s < Sn; s += 24) {
        const float* xp = tok + (size_t)s * Dn;
        float xv[24];
        float sum = 0.f, sq = 0.f;
        #pragma unroll
        for (int i = 0; i < 24; i++) {
            float v = xp[lane + 32 * i];
            xv[i] = v; sum += v; sq += v * v;
        }
        sum = warpRedSum(sum);
        sq = warpRedSum(sq);
        float m = sum * (1.f / 768.f);
        float var = sq * (1.f / 768.f) - m * m;
        float rstd = rsqrtf(var + 1e-5f);
        float d0 = 0.f, d1 = 0.f, d2 = 0.f, d3 = 0.f, dob = 0.f;
        #pragma unroll
        for (int i = 0; i < 24; i++) {
            int d = lane + 32 * i;
            float n = (xv[i] - m) * rstd * s_lnw[d] + s_lnb[d];
            d0 += n * s_wk[d];
            d1 += n * s_wk[Dn + d];
            d2 += n * s_wk[2 * Dn + d];
            d3 += n * s_wk[3 * Dn + d];
            dob += n * s_objw[d];
        }
        d0 = warpRedSum(d0); d1 = warpRedSum(d1);
        d2 = warpRedSum(d2); d3 = warpRedSum(d3);
        dob = warpRedSum(dob);
        if (lane == 0) {
            s_sc[0 * Sn + s] = (d0 + s_sbias[0]) * RSQRT_DH;
            s_sc[1 * Sn + s] = (d1 + s_sbias[1]) * RSQRT_DH;
            s_sc[2 * Sn + s] = (d2 + s_sbias[2]) * RSQRT_DH;
            s_sc[3 * Sn + s] = (d3 + s_sbias[3]) * RSQRT_DH;
            s_obj[s] = dob + obj_b[0];
            s_m[s] = m; s_r[s] = rstd;
        }
    }
    __syncthreads();

    // ---- phase 2a: per-head softmax (warps 0..3); others: tables, zero lw --
    if (wid < NHn) {
        int h = wid;
        float mx = -1e30f;
        for (int s = lane; s < Sn; s += 32) mx = fmaxf(mx, s_sc[h * Sn + s]);
        mx = warpRedMax(mx);
        float sum = 0.f;
        for (int s = lane; s < Sn; s += 32) {
            float e = expf(s_sc[h * Sn + s] - mx);
            s_sc[h * Sn + s] = e; sum += e;
        }
        sum = warpRedSum(sum);
        float inv = 1.f / sum;
        for (int s = lane; s < Sn; s += 32) s_sc[h * Sn + s] *= inv;
    } else if (tid >= 128 && tid < 128 + GUPn) {
        int u = tid - 128;
        float src = fmaxf((u + 0.5f) * 0.25f - 0.5f, 0.f);
        int i0 = min((int)floorf(src), Gn - 1);
        int i1 = min(i0 + 1, Gn - 1);
        float w1 = src - (float)i0;
        s_i0[u] = i0; s_i1[u] = i1; s_w0[u] = 1.f - w1; s_w1[u] = w1;
    } else if (tid >= 192 && tid < 192 + Sn) {
        s_lw[tid - 192] = 0.f;
    }
    __syncthreads();

    // ---- phase 2b: bilinear upsample 14->56 ----
    for (int idx = tid; idx < UPN; idx += 768) {
        int u = idx / GUPn, v = idx - u * GUPn;
        int a0 = s_i0[u], a1 = s_i1[u], b0 = s_i0[v], b1 = s_i1[v];
        float r0 = s_w0[v] * s_obj[a0 * Gn + b0] + s_w1[v] * s_obj[a0 * Gn + b1];
        float r1 = s_w0[v] * s_obj[a1 * Gn + b0] + s_w1[v] * s_obj[a1 * Gn + b1];
        s_up[idx] = s_w0[u] * r0 + s_w1[u] * r1;
    }
    __syncthreads();

    // ---- phase 2c: spatial softmax + expected coords ----
    float Ttemp = fmaxf(temperature[0], 1.f);
    float lmax = -1e30f;
    for (int idx = tid; idx < UPN; idx += 768) lmax = fmaxf(lmax, s_up[idx]);
    float M = blockRedMax(lmax, s_red);
    float ls = 0.f, lcx = 0.f, lcy = 0.f;
    for (int idx = tid; idx < UPN; idx += 768) {
        int u = idx / GUPn, v = idx - u * GUPn;
        float e = expf((s_up[idx] - M) * Ttemp);
        ls += e;
        lcx += e * ((v + 0.5f) * (1.f / GUPn));
        lcy += e * ((u + 0.5f) * (1.f / GUPn));
    }
    blockRed3(ls, lcx, lcy, s_red);
    float cx0 = lcx / ls, cy0 = lcy / ls;
    if (tid == 0) {
        g_cxy0[bt * 2] = cx0;
        g_cxy0[bt * 2 + 1] = cy0;
        int cxg = (int)clampf(cx0 * (float)Gn, 0.f, (float)(Gn - 1));
        int cyg = (int)clampf(cy0 * (float)Gn, 0.f, (float)(Gn - 1));
        for (int dy = -1; dy <= 1; dy++)
            for (int dx = -1; dx <= 1; dx++) {
                int gy = min(max(cyg + dy, 0), Gn - 1);
                int gx = min(max(cxg + dx, 0), Gn - 1);
                s_lw[gy * Gn + gx] += 1.f / 9.f;
            }
    }
    __syncthreads();

    // ---- phase 3: d-parallel resweep (L2-hot) -> pooledX + local ----
    {
        int d = tid;
        float a0 = 0.f, a1 = 0.f, a2 = 0.f, a3 = 0.f, la = 0.f;
        float lw = s_lnw[d], lb = s_lnb[d];
        const float* xp = tok + d;
        for (int s = 0; s < Sn; s++) {
            float n = (xp[(size_t)s * Dn] - s_m[s]) * s_r[s] * lw + lb;
            a0 += s_sc[0 * Sn + s] * n;
            a1 += s_sc[1 * Sn + s] * n;
            a2 += s_sc[2 * Sn + s] * n;
            a3 += s_sc[3 * Sn + s] * n;
            la += s_lw[s] * n;
        }
        float* px = g_pooledX + (size_t)bt * (NHn * Dn);
        px[0 * Dn + d] = a0;
        px[1 * Dn + d] = a1;
        px[2 * Dn + d] = a2;
        px[3 * Dn + d] = a3;
        g_local[bt * Dn + d] = la;
    }
}

// ---------------- k-split tiled GEMM: partial[m,n] = sum_k A[m,k]*B[n,k] ----
// 64x64 tile, BK=16, 4x4 micro. blockIdx.z = k-slice (writes to g_part).
// flags: 1 = gelu(A element), 2 = head-block-diag A (offset (n0/192)*768)
__global__ void __launch_bounds__(256) k_tgemm_ks(int a_id, int lda,
                                                  const float* __restrict__ B, int ldb,
                                                  int N, int Kslice, int flags) {
    __shared__ float As[16][68], Bs[16][68];
    const float* A = scratch_ptr(a_id);
    float* P = g_part + (size_t)blockIdx.z * (BT * N);
    int tid = threadIdx.x;
    int m0 = blockIdx.y * 64, n0 = blockIdx.x * 64;
    int kbase = blockIdx.z * Kslice;
    int aoff = (flags & 2) ? (n0 / 192) * Dn : 0;
    int tx = tid & 15, ty = tid >> 4;   // 16x16 thread grid
    float acc[4][4] = {};
    for (int k0 = 0; k0 < Kslice; k0 += 16) {
        #pragma unroll
        for (int i = 0; i < 4; i++) {
            int idx = tid + i * 256;            // 0..1023
            int mm = idx >> 4, kk = idx & 15;   // 64 rows x 16 cols
            float a = A[(size_t)(m0 + mm) * lda + aoff + kbase + k0 + kk];
            if (flags & 1) a = geluf(a);
            As[kk][mm] = a;
            Bs[kk][mm] = B[(size_t)(n0 + mm) * ldb + kbase + k0 + kk];
        }
        __syncthreads();
        #pragma unroll
        for (int kk = 0; kk < 16; kk++) {
            float av[4], bv[4];
            #pragma unroll
            for (int i = 0; i < 4; i++) { av[i] = As[kk][ty * 4 + i]; bv[i] = Bs[kk][tx * 4 + i]; }
            #pragma unroll
            for (int i = 0; i < 4; i++)
                #pragma unroll
                for (int j = 0; j < 4; j++)
                    acc[i][j] += av[i] * bv[j];
        }
        __syncthreads();
    }
    #pragma unroll
    for (int i = 0; i < 4; i++)
        #pragma unroll
        for (int j = 0; j < 4; j++)
            P[(size_t)(m0 + ty * 4 + i) * N + n0 + tx * 4 + j] = acc[i][j];
}

// ---------------- deterministic slice reduce: C = sum_z part[z] + bias ------
__global__ void __launch_bounds__(256) k_reduce(int c_id, const float* __restrict__ bias,
                                                int N, int total, int nz) {
    float* C = scratch_ptr(c_id);
    int idx = blockIdx.x * 256 + threadIdx.x;
    if (idx >= total) return;
    float s = 0.f;
    for (int z = 0; z < nz; z++) s += g_part[(size_t)z * total + idx];
    C[idx] = s + bias[idx % N];
}

// ---------------- LN(ctx2) + concat local -> A1 ----------------------------
__global__ void __launch_bounds__(768) k_ln_cat(const float* __restrict__ anw,
                                                const float* __restrict__ anb) {
    __shared__ float red[96];
    int bt = blockIdx.x, tid = threadIdx.x;
    float x = g_ctx2[bt * Dn + tid];
    float s = x, sq = x * x;
    blockRed2(s, sq, red);
    float m = s * (1.f / 768.f);
    float var = sq * (1.f / 768.f) - m * m;
    float r = rsqrtf(var + 1e-5f);
    g_A1[bt * (2 * Dn) + tid] = (x - m) * r * anw[tid] + anb[tid];
    g_A1[bt * (2 * Dn) + Dn + tid] = g_local[bt * Dn + tid];
}

// ---------------- delta head: r3 + coarse refine ---------------------------
__global__ void __launch_bounds__(128) k_delta(const float* __restrict__ r3w,
                                               const float* __restrict__ r3b) {
    int bt = blockIdx.x, tid = threadIdx.x;
    float h = geluf(g_h2[bt * 128 + tid]);
    float d0 = h * r3w[tid];
    float d1 = h * r3w[128 + tid];
    __shared__ float rs[8];
    d0 = warpRedSum(d0); d1 = warpRedSum(d1);
    if ((tid & 31) == 0) { rs[(tid >> 5) * 2] = d0; rs[(tid >> 5) * 2 + 1] = d1; }
    __syncthreads();
    if (tid == 0) {
        float s0 = rs[0] + rs[2] + rs[4] + rs[6] + r3b[0];
        float s1 = rs[1] + rs[3] + rs[5] + rs[7] + r3b[1];
        float cx = clampf(g_cxy0[bt * 2] + 0.3f * tanhf(s0), 0.f, 1.f);
        float cy = clampf(g_cxy0[bt * 2 + 1] + 0.3f * tanhf(s1), 0.f, 1.f);
        g_cxy0[bt * 2] = cx;
        g_cxy0[bt * 2 + 1] = cy;
    }
}

// ---------------- temporal convs + box assembly ----------------------------
__global__ void __launch_bounds__(64) k_conv_final(const float* __restrict__ tc1w,
                                                   const float* __restrict__ tc1b,
                                                   const float* __restrict__ tc2w,
                                                   const float* __restrict__ tc2b,
                                                   const float* __restrict__ fbwh,
                                                   float* __restrict__ out) {
    __shared__ float seq[2][16], t1s[32][16], tds[2][16];
    int b = blockIdx.x, tid = threadIdx.x;
    if (tid < 32) {
        int i = tid >> 4, t = tid & 15;
        seq[i][t] = g_cxy0[(b * 16 + t) * 2 + i];
    }
    __syncthreads();
    if (tid < 32) {
        int c = tid;
        for (int t = 0; t < 16; t++) {
            float acc = tc1b[c];
            #pragma unroll
            for (int i = 0; i < 2; i++)
                #pragma unroll
                for (int k = 0; k < 5; k++) {
                    int tt = t + k - 2;
                    if (tt >= 0 && tt < 16) acc += seq[i][tt] * tc1w[c * 10 + i * 5 + k];
                }
            t1s[c][t] = geluf(acc);
        }
    }
    __syncthreads();
    if (tid < 32) {
        int o = tid >> 4, t = tid & 15;
        float acc = tc2b[o];
        for (int c = 0; c < 32; c++)
            #pragma unroll
            for (int k = 0; k < 5; k++) {
                int tt = t + k - 2;
                if (tt >= 0 && tt < 16) acc += t1s[c][tt] * tc2w[o * 160 + c * 5 + k];
            }
        tds[o][t] = acc;
    }
    __syncthreads();
    if (tid < 16) {
        int t = tid, bt = b * 16 + t;
        const float minsz = 1.0f / 14.0f;
        float cx = clampf(g_cxy0[bt * 2] + 0.12f * tanhf(tds[0][t]), 0.f, 1.f);
        float cy = clampf(g_cxy0[bt * 2 + 1] + 0.12f * tanhf(tds[1][t]), 0.f, 1.f);
        float w = clampf(fbwh[0], minsz, 1.f);
        float hh = clampf(fbwh[1], minsz, 1.f);
        float x1 = clampf(cx - 0.5f * w, 0.f, 1.f);
        float y1 = clampf(cy - 0.5f * hh, 0.f, 1.f);
        float x2 = clampf(cx + 0.5f * w, 0.f, 1.f);
        float y2 = clampf(cy + 0.5f * hh, 0.f, 1.f);
        x2 = clampf(fmaxf(x2, x1 + minsz), 0.f, 1.f);
        y2 = clampf(fmaxf(y2, y1 + minsz), 0.f, 1.f);
        out[bt * 4 + 0] = x1;
        out[bt * 4 + 1] = y1;
        out[bt * 4 + 2] = x2;
        out[bt * 4 + 3] = y2;
    }
}

// ---------------- launch --------------------------------------------------
extern "C" void kernel_launch(void* const* d_in, const int* in_sizes, int n_in,
                              void* d_out, int out_size) {
    const float* tokens = (const float*)d_in[0];
    const float* fbwh   = (const float*)d_in[2];
    const float* ln_w   = (const float*)d_in[3];
    const float* ln_b   = (const float*)d_in[4];
    const float* query  = (const float*)d_in[5];
    const float* ipw    = (const float*)d_in[6];
    const float* ipb    = (const float*)d_in[7];
    const float* out_w  = (const float*)d_in[8];
    const float* out_b  = (const float*)d_in[9];
    const float* an_w   = (const float*)d_in[10];
    const float* an_b   = (const float*)d_in[11];
    const float* obj_w  = (const float*)d_in[12];
    const float* obj_b  = (const float*)d_in[13];
    const float* temp   = (const float*)d_in[14];
    const float* r1_w   = (const float*)d_in[15];
    const float* r1_b   = (const float*)d_in[16];
    const float* r2_w   = (const float*)d_in[17];
    const float* r2_b   = (const float*)d_in[18];
    const float* r3_w   = (const float*)d_in[19];
    const float* r3_b   = (const float*)d_in[20];
    const float* tc1_w  = (const float*)d_in[21];
    const float* tc1_b  = (const float*)d_in[22];
    const float* tc2_w  = (const float*)d_in[23];
    const float* tc2_b  = (const float*)d_in[24];
    float* out = (float*)d_out;

    k_prep_qh<<<Dn, 128>>>(query, ipw, ipb);
    k_prep_wk2<<<NHn, 768>>>(ipw, ipb);

    // fused LN + scores + softmax + spatial + pooled/local
    k_main<<<BT, 768>>>(tokens, ln_w, ln_b, obj_w, obj_b, temp);

    // G1: ctx = pooledX (block-diag, id 0) @ Wv^T + bv -> g_ctx (id 1)
    k_tgemm_ks<<<dim3(12, 4, 4), 256>>>(0, NHn * Dn, ipw + (size_t)2 * Dn * Dn, Dn,
                                        Dn, 192, 2);
    k_reduce<<<(BT * Dn + 255) / 256, 256>>>(1, ipb + 2 * Dn, Dn, BT * Dn, 4);

    // G2: ctx2 = ctx (id 1) @ out_w^T + out_b -> g_ctx2 (id 2)
    k_tgemm_ks<<<dim3(12, 4, 4), 256>>>(1, Dn, out_w, Dn, Dn, 192, 0);
    k_reduce<<<(BT * Dn + 255) / 256, 256>>>(2, out_b, Dn, BT * Dn, 4);

    k_ln_cat<<<BT, 768>>>(an_w, an_b);

    // G3: h1_pre = A1 (id 3) @ r1_w^T + r1_b -> g_h1 (id 4)
    k_tgemm_ks<<<dim3(4, 4, 8), 256>>>(3, 2 * Dn, r1_w, 2 * Dn, 256, 192, 0);
    k_reduce<<<(BT * 256 + 255) / 256, 256>>>(4, r1_b, 256, BT * 256, 8);

    // G4: h2_pre = gelu(h1_pre) (id 4) @ r2_w^T + r2_b -> g_h2 (id 5)
    k_tgemm_ks<<<dim3(2, 4, 2), 256>>>(4, 256, r2_w, 256, 128, 128, 1);
    k_reduce<<<(BT * 128 + 255) / 256, 256>>>(5, r2_b, 128, BT * 128, 2);

    k_delta<<<BT, 128>>>(r3_w, r3_b);
    k_conv_final<<<Bn, 64>>>(tc1_w, tc1_b, tc2_w, tc2_b, fbwh, out);
}

// round 17
// speedup vs baseline: 3.2318x; 1.2259x over previous
#include <cuda_runtime.h>
#include <math.h>

// ---------------- problem constants ----------------
constexpr int Bn = 16, Tn = 16, Sn = 196, Dn = 768;
constexpr int NHn = 4, Gn = 14, GUPn = 56, UPN = GUPn * GUPn;
constexpr int BT = Bn * Tn;      // 256
constexpr float RSQRT_DH = 0.07216878364870323f;  // 1/sqrt(192)

#define DEV static __device__ __forceinline__

// ---------------- scratch (device globals; no allocations allowed) ----------
__device__ float g_qh[Dn];
__device__ float g_wk[NHn * Dn];
__device__ float g_sbias[NHn];
__device__ float g_cxy0[BT * 2];
__device__ float g_pooledX[BT * NHn * Dn];
__device__ float g_local[BT * Dn];
__device__ float g_ctx[BT * Dn];
__device__ float g_A1[BT * 2 * Dn];
__device__ float g_h1[BT * 256];
__device__ float g_part[8 * BT * Dn];   // k-split partials (8 x 256 x 768 floats)

// Scratch selector: device-side resolution of scratch buffers.
// NEVER pass __device__ globals as kernel args from host code — on GB300
// (ATS/HMM) the host shadow address is dereferenceable by the GPU and reads
// silently return zeros instead of faulting.
DEV float* scratch_ptr(int id) {
    switch (id) {
        case 0: return g_pooledX;
        case 1: return g_ctx;
        case 3: return g_A1;
        case 4: return g_h1;
        case 6: return g_part;
    }
    return nullptr;
}

// ---------------- helpers ----------------
DEV float warpRedSum(float v) {
    #pragma unroll
    for (int o = 16; o; o >>= 1) v += __shfl_xor_sync(0xffffffffu, v, o);
    return v;
}
DEV float warpRedMax(float v) {
    #pragma unroll
    for (int o = 16; o; o >>= 1) v = fmaxf(v, __shfl_xor_sync(0xffffffffu, v, o));
    return v;
}
// red must hold >= 96 floats
DEV float blockRedMax(float v, float* red) {
    int tid = threadIdx.x, w = tid >> 5, l = tid & 31, nw = blockDim.x >> 5;
    v = warpRedMax(v);
    if (l == 0) red[w] = v;
    __syncthreads();
    if (tid == 0) { float m = red[0]; for (int i = 1; i < nw; i++) m = fmaxf(m, red[i]); red[80] = m; }
    __syncthreads();
    v = red[80];
    __syncthreads();
    return v;
}
DEV void blockRed3(float& a, float& b, float& c, float* red) {
    int tid = threadIdx.x, w = tid >> 5, l = tid & 31, nw = blockDim.x >> 5;
    a = warpRedSum(a); b = warpRedSum(b); c = warpRedSum(c);
    if (l == 0) { red[w * 3] = a; red[w * 3 + 1] = b; red[w * 3 + 2] = c; }
    __syncthreads();
    if (tid == 0) {
        float sa = 0.f, sb = 0.f, sc = 0.f;
        for (int i = 0; i < nw; i++) { sa += red[i * 3]; sb += red[i * 3 + 1]; sc += red[i * 3 + 2]; }
        red[80] = sa; red[81] = sb; red[82] = sc;
    }
    __syncthreads();
    a = red[80]; b = red[81]; c = red[82];
    __syncthreads();
}
DEV float geluf(float x) { return 0.5f * x * (1.0f + erff(x * 0.70710678118654752f)); }
DEV float clampf(float x, float lo, float hi) { return fminf(fmaxf(x, lo), hi); }

// ---------------- K1a: qh[j] = query . Wq[j] + bq[j] ------------------------
__global__ void __launch_bounds__(128) k_prep_qh(const float* __restrict__ query,
                                                 const float* __restrict__ ipw,
                                                 const float* __restrict__ ipb) {
    int j = blockIdx.x, tid = threadIdx.x;
    float p = 0.f;
    const float* row = ipw + (size_t)j * Dn;
    for (int k = tid; k < Dn; k += 128) p += query[k] * row[k];
    __shared__ float r4[4];
    p = warpRedSum(p);
    if ((tid & 31) == 0) r4[tid >> 5] = p;
    __syncthreads();
    if (tid == 0) g_qh[j] = r4[0] + r4[1] + r4[2] + r4[3] + ipb[j];
}

// ---------------- K1b: wk_eff[h][d] = sum_j qh[h,j] * Wk[h*192+j][d] --------
__global__ void __launch_bounds__(768) k_prep_wk2(const float* __restrict__ ipw,
                                                  const float* __restrict__ ipb) {
    int h = blockIdx.x, tid = threadIdx.x;
    __shared__ float qs[192];
    if (tid < 192) qs[tid] = g_qh[h * 192 + tid];
    __syncthreads();
    float acc = 0.f;
    const float* base = ipw + (size_t)(Dn + h * 192) * Dn;
    for (int j = 0; j < 192; j++) acc += qs[j] * base[(size_t)j * Dn + tid];
    g_wk[h * Dn + tid] = acc;
    if (tid == 0) {
        float s = 0.f;
        for (int j = 0; j < 192; j++) s += qs[j] * ipb[Dn + h * 192 + j];
        g_sbias[h] = s;
    }
}

// ---------------- K2: fused big pass, one block per (b,t) -------------------
__global__ void __launch_bounds__(768) k_main(const float* __restrict__ tokens,
                                              const float* __restrict__ ln_w,
                                              const float* __restrict__ ln_b,
                                              const float* __restrict__ obj_w,
                                              const float* __restrict__ obj_b,
                                              const float* __restrict__ temperature) {
    __shared__ float s_lnw[Dn], s_lnb[Dn], s_objw[Dn];
    __shared__ float s_wk[NHn * Dn];
    __shared__ float s_sbias[NHn];
    __shared__ float s_m[Sn], s_r[Sn];
    __shared__ float s_sc[NHn * Sn];   // scores -> probs
    __shared__ float s_obj[Sn];
    __shared__ float s_up[UPN];
    __shared__ float s_lw[Sn];
    __shared__ int s_i0[GUPn], s_i1[GUPn];
    __shared__ float s_w0[GUPn], s_w1[GUPn];
    __shared__ float s_red[96];

    const int bt = blockIdx.x;
    const int tid = threadIdx.x;
    const int wid = tid >> 5, lane = tid & 31;
    const float* tok = tokens + (size_t)bt * Sn * Dn;

    // load constants
    s_lnw[tid] = ln_w[tid];
    s_lnb[tid] = ln_b[tid];
    s_objw[tid] = obj_w[tid];
    #pragma unroll
    for (int h = 0; h < NHn; h++) s_wk[h * Dn + tid] = g_wk[h * Dn + tid];
    if (tid < NHn) s_sbias[tid] = g_sbias[tid];
    __syncthreads();

    // ---- phase 1: warp-per-token LN + scores + obj ----
    for (int s = wid; s < Sn; s += 24) {
        const float* xp = tok + (size_t)s * Dn;
        float xv[24];
        float sum = 0.f, sq = 0.f;
        #pragma unroll
        for (int i = 0; i < 24; i++) {
            float v = xp[lane + 32 * i];
            xv[i] = v; sum += v; sq += v * v;
        }
        sum = warpRedSum(sum);
        sq = warpRedSum(sq);
        float m = sum * (1.f / 768.f);
        float var = sq * (1.f / 768.f) - m * m;
        float rstd = rsqrtf(var + 1e-5f);
        float d0 = 0.f, d1 = 0.f, d2 = 0.f, d3 = 0.f, dob = 0.f;
        #pragma unroll
        for (int i = 0; i < 24; i++) {
            int d = lane + 32 * i;
            float n = (xv[i] - m) * rstd * s_lnw[d] + s_lnb[d];
            d0 += n * s_wk[d];
            d1 += n * s_wk[Dn + d];
            d2 += n * s_wk[2 * Dn + d];
            d3 += n * s_wk[3 * Dn + d];
            dob += n * s_objw[d];
        }
        d0 = warpRedSum(d0); d1 = warpRedSum(d1);
        d2 = warpRedSum(d2); d3 = warpRedSum(d3);
        dob = warpRedSum(dob);
        if (lane == 0) {
            s_sc[0 * Sn + s] = (d0 + s_sbias[0]) * RSQRT_DH;
            s_sc[1 * Sn + s] = (d1 + s_sbias[1]) * RSQRT_DH;
            s_sc[2 * Sn + s] = (d2 + s_sbias[2]) * RSQRT_DH;
            s_sc[3 * Sn + s] = (d3 + s_sbias[3]) * RSQRT_DH;
            s_obj[s] = dob + obj_b[0];
            s_m[s] = m; s_r[s] = rstd;
        }
    }
    __syncthreads();

    // ---- phase 2a: per-head softmax (warps 0..3); others: tables, zero lw --
    if (wid < NHn) {
        int h = wid;
        float mx = -1e30f;
        for (int s = lane; s < Sn; s += 32) mx = fmaxf(mx, s_sc[h * Sn + s]);
        mx = warpRedMax(mx);
        float sum = 0.f;
        for (int s = lane; s < Sn; s += 32) {
            float e = expf(s_sc[h * Sn + s] - mx);
            s_sc[h * Sn + s] = e; sum += e;
        }
        sum = warpRedSum(sum);
        float inv = 1.f / sum;
        for (int s = lane; s < Sn; s += 32) s_sc[h * Sn + s] *= inv;
    } else if (tid >= 128 && tid < 128 + GUPn) {
        int u = tid - 128;
        float src = fmaxf((u + 0.5f) * 0.25f - 0.5f, 0.f);
        int i0 = min((int)floorf(src), Gn - 1);
        int i1 = min(i0 + 1, Gn - 1);
        float w1 = src - (float)i0;
        s_i0[u] = i0; s_i1[u] = i1; s_w0[u] = 1.f - w1; s_w1[u] = w1;
    } else if (tid >= 192 && tid < 192 + Sn) {
        s_lw[tid - 192] = 0.f;
    }
    __syncthreads();

    // ---- phase 2b: bilinear upsample 14->56 ----
    for (int idx = tid; idx < UPN; idx += 768) {
        int u = idx / GUPn, v = idx - u * GUPn;
        int a0 = s_i0[u], a1 = s_i1[u], b0 = s_i0[v], b1 = s_i1[v];
        float r0 = s_w0[v] * s_obj[a0 * Gn + b0] + s_w1[v] * s_obj[a0 * Gn + b1];
        float r1 = s_w0[v] * s_obj[a1 * Gn + b0] + s_w1[v] * s_obj[a1 * Gn + b1];
        s_up[idx] = s_w0[u] * r0 + s_w1[u] * r1;
    }
    __syncthreads();

    // ---- phase 2c: spatial softmax + expected coords ----
    float Ttemp = fmaxf(temperature[0], 1.f);
    float lmax = -1e30f;
    for (int idx = tid; idx < UPN; idx += 768) lmax = fmaxf(lmax, s_up[idx]);
    float M = blockRedMax(lmax, s_red);
    float ls = 0.f, lcx = 0.f, lcy = 0.f;
    for (int idx = tid; idx < UPN; idx += 768) {
        int u = idx / GUPn, v = idx - u * GUPn;
        float e = expf((s_up[idx] - M) * Ttemp);
        ls += e;
        lcx += e * ((v + 0.5f) * (1.f / GUPn));
        lcy += e * ((u + 0.5f) * (1.f / GUPn));
    }
    blockRed3(ls, lcx, lcy, s_red);
    float cx0 = lcx / ls, cy0 = lcy / ls;
    if (tid == 0) {
        g_cxy0[bt * 2] = cx0;
        g_cxy0[bt * 2 + 1] = cy0;
        int cxg = (int)clampf(cx0 * (float)Gn, 0.f, (float)(Gn - 1));
        int cyg = (int)clampf(cy0 * (float)Gn, 0.f, (float)(Gn - 1));
        for (int dy = -1; dy <= 1; dy++)
            for (int dx = -1; dx <= 1; dx++) {
                int gy = min(max(cyg + dy, 0), Gn - 1);
                int gx = min(max(cxg + dx, 0), Gn - 1);
                s_lw[gy * Gn + gx] += 1.f / 9.f;
            }
    }
    __syncthreads();

    // ---- phase 3: d-parallel resweep (L2-hot) -> pooledX + local ----
    {
        int d = tid;
        float a0 = 0.f, a1 = 0.f, a2 = 0.f, a3 = 0.f, la = 0.f;
        float lw = s_lnw[d], lb = s_lnb[d];
        const float* xp = tok + d;
        for (int s = 0; s < Sn; s++) {
            float n = (xp[(size_t)s * Dn] - s_m[s]) * s_r[s] * lw + lb;
            a0 += s_sc[0 * Sn + s] * n;
            a1 += s_sc[1 * Sn + s] * n;
            a2 += s_sc[2 * Sn + s] * n;
            a3 += s_sc[3 * Sn + s] * n;
            la += s_lw[s] * n;
        }
        float* px = g_pooledX + (size_t)bt * (NHn * Dn);
        px[0 * Dn + d] = a0;
        px[1 * Dn + d] = a1;
        px[2 * Dn + d] = a2;
        px[3 * Dn + d] = a3;
        g_local[bt * Dn + d] = la;
    }
}

// ---- k-split tiled GEMM with register double-buffering + float4 staging ----
// 64x64 tile, BK=16, 4x4 micro. blockIdx.z = k-slice -> g_part.
// flags: 1 = gelu(A element), 2 = head-block-diag A (offset (n0/192)*768)
// All lda/ldb/offsets are multiples of 4 floats -> float4 loads are aligned.
__global__ void __launch_bounds__(256) k_tgemm_ks(int a_id, int lda,
                                                  const float* __restrict__ B, int ldb,
                                                  int N, int Kslice, int flags) {
    __shared__ float As[2][16][68], Bs[2][16][68];
    const float* A = scratch_ptr(a_id);
    float* P = g_part + (size_t)blockIdx.z * (BT * N);
    int tid = threadIdx.x;
    int m0 = blockIdx.y * 64, n0 = blockIdx.x * 64;
    int kbase = blockIdx.z * Kslice;
    int aoff = (flags & 2) ? (n0 / 192) * Dn : 0;
    int tx = tid & 15, ty = tid >> 4;     // 16x16 compute grid
    int smm = tid >> 2;                   // staging row 0..63
    int skq = (tid & 3) * 4;              // staging k 0,4,8,12
    const float* Abase = A + (size_t)(m0 + smm) * lda + aoff + kbase + skq;
    const float* Bbase = B + (size_t)(n0 + smm) * ldb + kbase + skq;

    float4 ra = *reinterpret_cast<const float4*>(Abase);
    float4 rb = *reinterpret_cast<const float4*>(Bbase);
    if (flags & 1) { ra.x = geluf(ra.x); ra.y = geluf(ra.y); ra.z = geluf(ra.z); ra.w = geluf(ra.w); }
    As[0][skq + 0][smm] = ra.x; As[0][skq + 1][smm] = ra.y;
    As[0][skq + 2][smm] = ra.z; As[0][skq + 3][smm] = ra.w;
    Bs[0][skq + 0][smm] = rb.x; Bs[0][skq + 1][smm] = rb.y;
    Bs[0][skq + 2][smm] = rb.z; Bs[0][skq + 3][smm] = rb.w;
    __syncthreads();

    float acc[4][4] = {};
    int niter = Kslice >> 4;
    for (int it = 0; it < niter; it++) {
        int cur = it & 1;
        bool more = (it + 1 < niter);
        if (more) {
            ra = *reinterpret_cast<const float4*>(Abase + (it + 1) * 16);
            rb = *reinterpret_cast<const float4*>(Bbase + (it + 1) * 16);
            if (flags & 1) { ra.x = geluf(ra.x); ra.y = geluf(ra.y); ra.z = geluf(ra.z); ra.w = geluf(ra.w); }
        }
        #pragma unroll
        for (int kk = 0; kk < 16; kk++) {
            float av[4], bv[4];
            #pragma unroll
            for (int i = 0; i < 4; i++) { av[i] = As[cur][kk][ty * 4 + i]; bv[i] = Bs[cur][kk][tx * 4 + i]; }
            #pragma unroll
            for (int i = 0; i < 4; i++)
                #pragma unroll
                for (int j = 0; j < 4; j++)
                    acc[i][j] += av[i] * bv[j];
        }
        if (more) {
            int nb = cur ^ 1;
            As[nb][skq + 0][smm] = ra.x; As[nb][skq + 1][smm] = ra.y;
            As[nb][skq + 2][smm] = ra.z; As[nb][skq + 3][smm] = ra.w;
            Bs[nb][skq + 0][smm] = rb.x; Bs[nb][skq + 1][smm] = rb.y;
            Bs[nb][skq + 2][smm] = rb.z; Bs[nb][skq + 3][smm] = rb.w;
        }
        __syncthreads();
    }
    #pragma unroll
    for (int i = 0; i < 4; i++)
        #pragma unroll
        for (int j = 0; j < 4; j++)
            P[(size_t)(m0 + ty * 4 + i) * N + n0 + tx * 4 + j] = acc[i][j];
}

// ---------------- deterministic slice reduce: C = sum_z part[z] + bias ------
__global__ void __launch_bounds__(256) k_reduce(int c_id, const float* __restrict__ bias,
                                                int N, int total, int nz) {
    float* C = scratch_ptr(c_id);
    int idx = blockIdx.x * 256 + threadIdx.x;
    if (idx >= total) return;
    float s = 0.f;
    for (int z = 0; z < nz; z++) s += g_part[(size_t)z * total + idx];
    C[idx] = s + bias[idx % N];
}

// ---------------- LN(reduced ctx2) + concat local -> A1 ---------------------
// reduces G2's partials inline (ctx2 = sum_z part[z] + out_b), then LN + cat.
__global__ void __launch_bounds__(768) k_ln_cat(const float* __restrict__ anw,
                                                const float* __restrict__ anb,
                                                const float* __restrict__ cbias,
                                                int nz) {
    __shared__ float red[96];
    int bt = blockIdx.x, tid = threadIdx.x, w = tid >> 5, l = tid & 31;
    float x = cbias[tid];
    for (int z = 0; z < nz; z++) x += g_part[(size_t)z * (BT * Dn) + bt * Dn + tid];
    float s1 = warpRedSum(x), s2 = warpRedSum(x * x);
    if (l == 0) { red[w] = s1; red[24 + w] = s2; }
    __syncthreads();
    if (tid == 0) {
        float a = 0.f, b = 0.f;
        for (int i = 0; i < 24; i++) { a += red[i]; b += red[24 + i]; }
        red[80] = a; red[81] = b;
    }
    __syncthreads();
    float m = red[80] * (1.f / 768.f);
    float var = red[81] * (1.f / 768.f) - m * m;
    float r = rsqrtf(var + 1e-5f);
    g_A1[bt * (2 * Dn) + tid] = (x - m) * r * anw[tid] + anb[tid];
    g_A1[bt * (2 * Dn) + Dn + tid] = g_local[bt * Dn + tid];
}

// ---------------- delta head: reduce G4 partials + gelu + r3 + refine -------
__global__ void __launch_bounds__(128) k_delta(const float* __restrict__ r3w,
                                               const float* __restrict__ r3b,
                                               const float* __restrict__ hbias,
                                               int nz) {
    int bt = blockIdx.x, tid = threadIdx.x;
    float pre = hbias[tid];
    for (int z = 0; z < nz; z++) pre += g_part[(size_t)z * (BT * 128) + bt * 128 + tid];
    float h = geluf(pre);
    float d0 = h * r3w[tid];
    float d1 = h * r3w[128 + tid];
    __shared__ float rs[8];
    d0 = warpRedSum(d0); d1 = warpRedSum(d1);
    if ((tid & 31) == 0) { rs[(tid >> 5) * 2] = d0; rs[(tid >> 5) * 2 + 1] = d1; }
    __syncthreads();
    if (tid == 0) {
        float s0 = rs[0] + rs[2] + rs[4] + rs[6] + r3b[0];
        float s1 = rs[1] + rs[3] + rs[5] + rs[7] + r3b[1];
        float cx = clampf(g_cxy0[bt * 2] + 0.3f * tanhf(s0), 0.f, 1.f);
        float cy = clampf(g_cxy0[bt * 2 + 1] + 0.3f * tanhf(s1), 0.f, 1.f);
        g_cxy0[bt * 2] = cx;
        g_cxy0[bt * 2 + 1] = cy;
    }
}

// ---------------- temporal convs + box assembly ----------------------------
__global__ void __launch_bounds__(64) k_conv_final(const float* __restrict__ tc1w,
                                                   const float* __restrict__ tc1b,
                                                   const float* __restrict__ tc2w,
                                                   const float* __restrict__ tc2b,
                                                   const float* __restrict__ fbwh,
                                                   float* __restrict__ out) {
    __shared__ float seq[2][16], t1s[32][16], tds[2][16];
    int b = blockIdx.x, tid = threadIdx.x;
    if (tid < 32) {
        int i = tid >> 4, t = tid & 15;
        seq[i][t] = g_cxy0[(b * 16 + t) * 2 + i];
    }
    __syncthreads();
    if (tid < 32) {
        int c = tid;
        for (int t = 0; t < 16; t++) {
            float acc = tc1b[c];
            #pragma unroll
            for (int i = 0; i < 2; i++)
                #pragma unroll
                for (int k = 0; k < 5; k++) {
                    int tt = t + k - 2;
                    if (tt >= 0 && tt < 16) acc += seq[i][tt] * tc1w[c * 10 + i * 5 + k];
                }
            t1s[c][t] = geluf(acc);
        }
    }
    __syncthreads();
    if (tid < 32) {
        int o = tid >> 4, t = tid & 15;
        float acc = tc2b[o];
        for (int c = 0; c < 32; c++)
            #pragma unroll
            for (int k = 0; k < 5; k++) {
                int tt = t + k - 2;
                if (tt >= 0 && tt < 16) acc += t1s[c][tt] * tc2w[o * 160 + c * 5 + k];
            }
        tds[o][t] = acc;
    }
    __syncthreads();
    if (tid < 16) {
        int t = tid, bt = b * 16 + t;
        const float minsz = 1.0f / 14.0f;
        float cx = clampf(g_cxy0[bt * 2] + 0.12f * tanhf(tds[0][t]), 0.f, 1.f);
        float cy = clampf(g_cxy0[bt * 2 + 1] + 0.12f * tanhf(tds[1][t]), 0.f, 1.f);
        float w = clampf(fbwh[0], minsz, 1.f);
        float hh = clampf(fbwh[1], minsz, 1.f);
        float x1 = clampf(cx - 0.5f * w, 0.f, 1.f);
        float y1 = clampf(cy - 0.5f * hh, 0.f, 1.f);
        float x2 = clampf(cx + 0.5f * w, 0.f, 1.f);
        float y2 = clampf(cy + 0.5f * hh, 0.f, 1.f);
        x2 = clampf(fmaxf(x2, x1 + minsz), 0.f, 1.f);
        y2 = clampf(fmaxf(y2, y1 + minsz), 0.f, 1.f);
        out[bt * 4 + 0] = x1;
        out[bt * 4 + 1] = y1;
        out[bt * 4 + 2] = x2;
        out[bt * 4 + 3] = y2;
    }
}

// ---------------- launch --------------------------------------------------
extern "C" void kernel_launch(void* const* d_in, const int* in_sizes, int n_in,
                              void* d_out, int out_size) {
    const float* tokens = (const float*)d_in[0];
    const float* fbwh   = (const float*)d_in[2];
    const float* ln_w   = (const float*)d_in[3];
    const float* ln_b   = (const float*)d_in[4];
    const float* query  = (const float*)d_in[5];
    const float* ipw    = (const float*)d_in[6];
    const float* ipb    = (const float*)d_in[7];
    const float* out_w  = (const float*)d_in[8];
    const float* out_b  = (const float*)d_in[9];
    const float* an_w   = (const float*)d_in[10];
    const float* an_b   = (const float*)d_in[11];
    const float* obj_w  = (const float*)d_in[12];
    const float* obj_b  = (const float*)d_in[13];
    const float* temp   = (const float*)d_in[14];
    const float* r1_w   = (const float*)d_in[15];
    const float* r1_b   = (const float*)d_in[16];
    const float* r2_w   = (const float*)d_in[17];
    const float* r2_b   = (const float*)d_in[18];
    const float* r3_w   = (const float*)d_in[19];
    const float* r3_b   = (const float*)d_in[20];
    const float* tc1_w  = (const float*)d_in[21];
    const float* tc1_b  = (const float*)d_in[22];
    const float* tc2_w  = (const float*)d_in[23];
    const float* tc2_b  = (const float*)d_in[24];
    float* out = (float*)d_out;

    k_prep_qh<<<Dn, 128>>>(query, ipw, ipb);
    k_prep_wk2<<<NHn, 768>>>(ipw, ipb);

    // fused LN + scores + softmax + spatial + pooled/local
    k_main<<<BT, 768>>>(tokens, ln_w, ln_b, obj_w, obj_b, temp);

    // G1: ctx = pooledX (block-diag, id 0) @ Wv^T -> partials -> g_ctx (id 1)
    k_tgemm_ks<<<dim3(12, 4, 8), 256>>>(0, NHn * Dn, ipw + (size_t)2 * Dn * Dn, Dn,
                                        Dn, 96, 2);
    k_reduce<<<(BT * Dn + 255) / 256, 256>>>(1, ipb + 2 * Dn, Dn, BT * Dn, 8);

    // G2: ctx2 partials = ctx (id 1) @ out_w^T ; reduced inside k_ln_cat
    k_tgemm_ks<<<dim3(12, 4, 8), 256>>>(1, Dn, out_w, Dn, Dn, 96, 0);
    k_ln_cat<<<BT, 768>>>(an_w, an_b, out_b, 8);

    // G3: h1_pre = A1 (id 3) @ r1_w^T -> partials -> g_h1 (id 4)
    k_tgemm_ks<<<dim3(4, 4, 16), 256>>>(3, 2 * Dn, r1_w, 2 * Dn, 256, 96, 0);
    k_reduce<<<(BT * 256 + 255) / 256, 256>>>(4, r1_b, 256, BT * 256, 16);

    // G4: h2 partials = gelu(h1) (id 4) @ r2_w^T ; reduced inside k_delta
    k_tgemm_ks<<<dim3(2, 4, 4), 256>>>(4, 256, r2_w, 256, 128, 64, 1);
    k_delta<<<BT, 128>>>(r3_w, r3_b, r2_b, 4);

    k_conv_final<<<Bn, 64>>>(tc1_w, tc1_b, tc2_w, tc2_b, fbwh, out);
}